// round 16
// baseline (speedup 1.0000x reference)
#include <cuda_runtime.h>
#include <cuda_fp16.h>
#include <math.h>
#include <stdint.h>

#define BB 4
#define NN 2048
#define MM 2048
#define DQ 512
#define DC 768
#define HH 8
#define DH 64
#define INNER 512

// 0.125 * log2(e): folds attention scale + base-2 exp domain into Q projection.
#define QSCALE 0.18033688011112042f

// ---------------------------------------------------------------------------
// Scratch (device globals -- no allocation allowed)
// ---------------------------------------------------------------------------
__device__ __half g_xn[BB*NN*DQ];
__device__ __half g_cn[BB*MM*DC];
__device__ __half g_q [BB*NN*INNER];
__device__ __half g_k [BB*MM*INNER];
__device__ __half g_v [BB*MM*INNER];
__device__ __half g_ao[BB*NN*INNER];
__device__ float  g_y [BB*NN*DQ];
__device__ __half g_wq[DQ*INNER];
__device__ __half g_wk[DC*INNER];
__device__ __half g_wv[DC*INNER];
__device__ __half g_wo[INNER*DQ];

// ---------------------------------------------------------------------------
// PTX helpers
// ---------------------------------------------------------------------------
__device__ __forceinline__ uint32_t h2_as_u32(__half2 h) {
    return *reinterpret_cast<uint32_t*>(&h);
}
__device__ __forceinline__ void cp16g(void* dst_smem, const void* src) {
    uint32_t d = (uint32_t)__cvta_generic_to_shared(dst_smem);
    asm volatile("cp.async.cg.shared.global [%0], [%1], 16;" :: "r"(d), "l"(src));
}
__device__ __forceinline__ void cp_commit() {
    asm volatile("cp.async.commit_group;" ::: "memory");
}
__device__ __forceinline__ void cp_wait1() {
    asm volatile("cp.async.wait_group 1;" ::: "memory");
}
__device__ __forceinline__ void cp_wait2() {
    asm volatile("cp.async.wait_group 2;" ::: "memory");
}
__device__ __forceinline__ void ldsm4(uint32_t& r0, uint32_t& r1, uint32_t& r2, uint32_t& r3, uint32_t a) {
    asm volatile("ldmatrix.sync.aligned.m8n8.x4.shared.b16 {%0,%1,%2,%3}, [%4];"
                 : "=r"(r0), "=r"(r1), "=r"(r2), "=r"(r3) : "r"(a));
}
__device__ __forceinline__ void ldsm4t(uint32_t& r0, uint32_t& r1, uint32_t& r2, uint32_t& r3, uint32_t a) {
    asm volatile("ldmatrix.sync.aligned.m8n8.x4.trans.shared.b16 {%0,%1,%2,%3}, [%4];"
                 : "=r"(r0), "=r"(r1), "=r"(r2), "=r"(r3) : "r"(a));
}
__device__ __forceinline__ void mma16(float* c, uint32_t a0, uint32_t a1, uint32_t a2, uint32_t a3,
                                      uint32_t b0, uint32_t b1) {
    asm volatile(
        "mma.sync.aligned.m16n8k16.row.col.f32.f16.f16.f32 "
        "{%0,%1,%2,%3},{%4,%5,%6,%7},{%8,%9},{%0,%1,%2,%3};"
        : "+f"(c[0]), "+f"(c[1]), "+f"(c[2]), "+f"(c[3])
        : "r"(a0), "r"(a1), "r"(a2), "r"(a3), "r"(b0), "r"(b1));
}

// all-ones fp16x2 B fragment (1.0, 1.0)
#define H2_ONES 0x3C003C00u

// ---------------------------------------------------------------------------
// Fused prep: input LayerNorms (warp-per-row) + weight f2h, one launch.
// ---------------------------------------------------------------------------
#define LN_ROWS (BB*NN + BB*MM)          // 16384
#define LN_BLK  (LN_ROWS / 8)            // 2048
#define N4_WQ (DQ*INNER/4)
#define N4_WK (DC*INNER/4)
#define N4_WV (DC*INNER/4)
#define N4_WO (INNER*DQ/4)
#define N4_TOT (N4_WQ + N4_WK + N4_WV + N4_WO)   // 327680
#define F2H_BLK ((N4_TOT + 255) / 256)   // 1280

__global__ __launch_bounds__(256) void prep_kernel(
    const float* __restrict__ x,    const float* __restrict__ xg, const float* __restrict__ xb,
    const float* __restrict__ cnd,  const float* __restrict__ cg, const float* __restrict__ cb,
    const float4* __restrict__ wq, const float4* __restrict__ wk,
    const float4* __restrict__ wv, const float4* __restrict__ wo)
{
    if (blockIdx.x >= LN_BLK) {
        int i = (blockIdx.x - LN_BLK) * blockDim.x + threadIdx.x;
        if (i >= N4_TOT) return;
        const float4* src;
        __half2* dst;
        int j = i;
        if (j < N4_WQ)                 { src = wq; dst = (__half2*)g_wq; }
        else if ((j -= N4_WQ) < N4_WK) { src = wk; dst = (__half2*)g_wk; }
        else if ((j -= N4_WK) < N4_WV) { src = wv; dst = (__half2*)g_wv; }
        else { j -= N4_WV;               src = wo; dst = (__half2*)g_wo; }
        float4 v = src[j];
        dst[2*j]   = __floats2half2_rn(v.x, v.y);
        dst[2*j+1] = __floats2half2_rn(v.z, v.w);
        return;
    }

    const int warp = threadIdx.x >> 5, lane = threadIdx.x & 31;
    int row = blockIdx.x * 8 + warp;

    const float* in; const float* gw; const float* bw; __half* out; int D;
    if (row < BB * NN) { in = x; gw = xg; bw = xb; out = g_xn; D = DQ; }
    else { row -= BB * NN; in = cnd; gw = cg; bw = cb; out = g_cn; D = DC; }
    const int nv = D / 128;

    const float4* x4 = (const float4*)(in + (size_t)row * D);
    float4 v[6];
    float s = 0.f, sq = 0.f;
    #pragma unroll 6
    for (int i = 0; i < nv; i++) {
        v[i] = x4[lane + 32 * i];
        s  += v[i].x + v[i].y + v[i].z + v[i].w;
        sq += v[i].x * v[i].x + v[i].y * v[i].y + v[i].z * v[i].z + v[i].w * v[i].w;
    }
    #pragma unroll
    for (int off = 16; off; off >>= 1) {
        s  += __shfl_xor_sync(0xffffffffu, s,  off);
        sq += __shfl_xor_sync(0xffffffffu, sq, off);
    }
    const float mu   = s * (1.0f / D);
    const float var  = sq * (1.0f / D) - mu * mu;
    const float rstd = rsqrtf(var + 1e-5f);

    const float4* g4 = (const float4*)gw;
    const float4* b4 = (const float4*)bw;
    __half2* o2 = (__half2*)out + (size_t)row * (D / 2);
    #pragma unroll 6
    for (int i = 0; i < nv; i++) {
        float4 g = g4[lane + 32 * i], b = b4[lane + 32 * i];
        float rx = (v[i].x - mu) * rstd * g.x + b.x;
        float ry = (v[i].y - mu) * rstd * g.y + b.y;
        float rz = (v[i].z - mu) * rstd * g.z + b.z;
        float rw = (v[i].w - mu) * rstd * g.w + b.w;
        o2[(lane + 32 * i) * 2]     = __floats2half2_rn(rx, ry);
        o2[(lane + 32 * i) * 2 + 1] = __floats2half2_rn(rz, rw);
    }
}

// Warp-per-row final LayerNorm (fp32 in/out, D=512)
__global__ __launch_bounds__(256) void ln_out(
    const float* __restrict__ in, const float* __restrict__ gw,
    const float* __restrict__ bw, float* __restrict__ outp)
{
    const int warp = threadIdx.x >> 5, lane = threadIdx.x & 31;
    const int row = blockIdx.x * 8 + warp;

    const float4* x4 = (const float4*)(in + (size_t)row * DQ);
    float4 v[4];
    float s = 0.f, sq = 0.f;
    #pragma unroll
    for (int i = 0; i < 4; i++) {
        v[i] = x4[lane + 32 * i];
        s  += v[i].x + v[i].y + v[i].z + v[i].w;
        sq += v[i].x * v[i].x + v[i].y * v[i].y + v[i].z * v[i].z + v[i].w * v[i].w;
    }
    #pragma unroll
    for (int off = 16; off; off >>= 1) {
        s  += __shfl_xor_sync(0xffffffffu, s,  off);
        sq += __shfl_xor_sync(0xffffffffu, sq, off);
    }
    const float mu   = s * (1.0f / DQ);
    const float var  = sq * (1.0f / DQ) - mu * mu;
    const float rstd = rsqrtf(var + 1e-5f);

    const float4* g4 = (const float4*)gw;
    const float4* b4 = (const float4*)bw;
    float4* o4 = (float4*)(outp + (size_t)row * DQ);
    #pragma unroll
    for (int i = 0; i < 4; i++) {
        float4 g = g4[lane + 32 * i], b = b4[lane + 32 * i], r;
        r.x = (v[i].x - mu) * rstd * g.x + b.x;
        r.y = (v[i].y - mu) * rstd * g.y + b.y;
        r.z = (v[i].z - mu) * rstd * g.z + b.z;
        r.w = (v[i].w - mu) * rstd * g.w + b.w;
        o4[lane + 32 * i] = r;
    }
}

// ---------------------------------------------------------------------------
// GEMM tile config (qkv: 128x128, 3-stage)
// ---------------------------------------------------------------------------
#define GS_A 9216                      // 128*72 halves
#define GS_B 8704                      // 64*136 halves
#define GSTG (GS_A + GS_B)             // 17920 halves / stage
#define GEMM_SMEM (3 * GSTG * 2)       // 107520 bytes

// ---------------------------------------------------------------------------
// Merged Q/K/V projection: LPT order (long K/V first, short Q last).
// ---------------------------------------------------------------------------
__global__ __launch_bounds__(256, 2) void qkv_gemm()
{
    extern __shared__ __half smh[];
    const uint32_t sbase = (uint32_t)__cvta_generic_to_shared(smh);

    const __half* A; const __half* W; __half* C; int K; float osc;
    if (blockIdx.z == 0)      { A = g_cn; W = g_wk; C = g_k; K = DC; osc = 1.0f; }
    else if (blockIdx.z == 1) { A = g_cn; W = g_wv; C = g_v; K = DC; osc = 1.0f; }
    else                      { A = g_xn; W = g_wq; C = g_q; K = DQ; osc = QSCALE; }

    const int tid = threadIdx.x;
    const int lane = tid & 31, warp = tid >> 5;
    const int wm = (warp >> 2) * 64;
    const int wn = (warp & 3) * 32;
    const int m0 = blockIdx.y * 128;
    const int n0 = blockIdx.x * 128;
    const int g = lane >> 2, t = lane & 3;

    const int a_row = lane & 15, a_col = (lane >> 4) * 8;
    const int b_row = (lane & 7) + ((lane >> 3) & 1) * 8;
    const int b_col = ((lane >> 4) & 1) * 8;

    float acc[4][4][4];
    #pragma unroll
    for (int i = 0; i < 4; i++)
        #pragma unroll
        for (int j = 0; j < 4; j++)
            #pragma unroll
            for (int q = 0; q < 4; q++) acc[i][j][q] = 0.f;

    auto load_tile = [&](int kt, int buf) {
        int k0 = kt * 64;
        __half* As = smh + buf * GSTG;
        __half* Bs = smh + buf * GSTG + GS_A;
        #pragma unroll
        for (int i = 0; i < 4; i++) {
            int id = tid + i * 256;
            int ar = id >> 3, ac = (id & 7) * 8;
            cp16g(&As[ar * 72 + ac], &A[(size_t)(m0 + ar) * K + k0 + ac]);
            int br = id >> 4, bc = (id & 15) * 8;
            cp16g(&Bs[br * 136 + bc], &W[(size_t)(k0 + br) * INNER + n0 + bc]);
        }
    };

    const int ntiles = K / 64;
    load_tile(0, 0); cp_commit();
    load_tile(1, 1); cp_commit();
    cp_wait1();
    __syncthreads();

    for (int kt = 0; kt < ntiles; kt++) {
        const int cur = kt % 3;
        if (kt + 2 < ntiles) load_tile(kt + 2, (kt + 2) % 3);
        cp_commit();

        const uint32_t abase = sbase + (uint32_t)(cur * GSTG) * 2;
        const uint32_t bbase = abase + (uint32_t)GS_A * 2;

        #pragma unroll
        for (int ks = 0; ks < 4; ks++) {
            uint32_t af[4][4];
            #pragma unroll
            for (int mt = 0; mt < 4; mt++) {
                uint32_t addr = abase +
                    (uint32_t)(((wm + mt * 16 + a_row) * 72 + ks * 16 + a_col) << 1);
                ldsm4(af[mt][0], af[mt][1], af[mt][2], af[mt][3], addr);
            }
            uint32_t bf[8];
            #pragma unroll
            for (int n2 = 0; n2 < 2; n2++) {
                uint32_t addr = bbase +
                    (uint32_t)(((ks * 16 + b_row) * 136 + wn + n2 * 16 + b_col) << 1);
                ldsm4t(bf[n2*4], bf[n2*4+1], bf[n2*4+2], bf[n2*4+3], addr);
            }
            #pragma unroll
            for (int mt = 0; mt < 4; mt++)
                #pragma unroll
                for (int nt = 0; nt < 4; nt++)
                    mma16(acc[mt][nt], af[mt][0], af[mt][1], af[mt][2], af[mt][3],
                          bf[nt*2], bf[nt*2+1]);
        }

        cp_wait1();
        __syncthreads();
    }

    #pragma unroll
    for (int mt = 0; mt < 4; mt++) {
        int row = m0 + wm + mt * 16 + g;
        #pragma unroll
        for (int nt = 0; nt < 4; nt++) {
            int col = n0 + wn + nt * 8 + 2 * t;
            *(__half2*)&C[(size_t)row * INNER + col] =
                __floats2half2_rn(acc[mt][nt][0] * osc, acc[mt][nt][1] * osc);
            *(__half2*)&C[(size_t)(row + 8) * INNER + col] =
                __floats2half2_rn(acc[mt][nt][2] * osc, acc[mt][nt][3] * osc);
        }
    }
}

// ---------------------------------------------------------------------------
// O-projection GEMM: 64x128 CTA tile, 2-stage pipeline, 3 CTAs/SM.
// Warp tile 32x32 (2 m-tiles x 4 n-tiles). fp32 out + bias + residual.
// ---------------------------------------------------------------------------
#define OS_A 4608                      // 64*72 halves
#define OS_B 8704                      // 64*136 halves
#define OSTG (OS_A + OS_B)             // 13312 halves / stage
#define GEMMO_SMEM (2 * OSTG * 2)      // 53248 bytes

__global__ __launch_bounds__(256, 3) void gemm_o(
    const float* __restrict__ bias, const float* __restrict__ resid)
{
    extern __shared__ __half smh[];
    const uint32_t sbase = (uint32_t)__cvta_generic_to_shared(smh);
    const __half* A = g_ao;
    const __half* W = g_wo;
    float* Cf = g_y;
    const int K = INNER, N = DQ;

    const int tid = threadIdx.x;
    const int lane = tid & 31, warp = tid >> 5;
    const int wm = (warp >> 2) * 32;
    const int wn = (warp & 3) * 32;
    const int m0 = blockIdx.y * 64;
    const int n0 = blockIdx.x * 128;
    const int g = lane >> 2, t = lane & 3;

    const int a_row = lane & 15, a_col = (lane >> 4) * 8;
    const int b_row = (lane & 7) + ((lane >> 3) & 1) * 8;
    const int b_col = ((lane >> 4) & 1) * 8;

    float acc[2][4][4];
    #pragma unroll
    for (int i = 0; i < 2; i++)
        #pragma unroll
        for (int j = 0; j < 4; j++)
            #pragma unroll
            for (int q = 0; q < 4; q++) acc[i][j][q] = 0.f;

    auto load_tile = [&](int kt, int buf) {
        int k0 = kt * 64;
        __half* As = smh + buf * OSTG;
        __half* Bs = smh + buf * OSTG + OS_A;
        #pragma unroll
        for (int i = 0; i < 2; i++) {
            int id = tid + i * 256;
            int ar = id >> 3, ac = (id & 7) * 8;
            cp16g(&As[ar * 72 + ac], &A[(size_t)(m0 + ar) * K + k0 + ac]);
        }
        #pragma unroll
        for (int i = 0; i < 4; i++) {
            int id = tid + i * 256;
            int br = id >> 4, bc = (id & 15) * 8;
            cp16g(&Bs[br * 136 + bc], &W[(size_t)(k0 + br) * N + n0 + bc]);
        }
    };

    const int ntiles = K / 64;           // 8
    load_tile(0, 0); cp_commit();
    load_tile(1, 1); cp_commit();
    cp_wait1();                          // tile 0 resident
    __syncthreads();

    for (int kt = 0; kt < ntiles; kt++) {
        const int cur = kt & 1;
        const uint32_t abase = sbase + (uint32_t)(cur * OSTG) * 2;
        const uint32_t bbase = abase + (uint32_t)OS_A * 2;

        #pragma unroll
        for (int ks = 0; ks < 4; ks++) {
            uint32_t af[2][4];
            #pragma unroll
            for (int mt = 0; mt < 2; mt++) {
                uint32_t addr = abase +
                    (uint32_t)(((wm + mt * 16 + a_row) * 72 + ks * 16 + a_col) << 1);
                ldsm4(af[mt][0], af[mt][1], af[mt][2], af[mt][3], addr);
            }
            uint32_t bf[8];
            #pragma unroll
            for (int n2 = 0; n2 < 2; n2++) {
                uint32_t addr = bbase +
                    (uint32_t)(((ks * 16 + b_row) * 136 + wn + n2 * 16 + b_col) << 1);
                ldsm4t(bf[n2*4], bf[n2*4+1], bf[n2*4+2], bf[n2*4+3], addr);
            }
            #pragma unroll
            for (int mt = 0; mt < 2; mt++)
                #pragma unroll
                for (int nt = 0; nt < 4; nt++)
                    mma16(acc[mt][nt], af[mt][0], af[mt][1], af[mt][2], af[mt][3],
                          bf[nt*2], bf[nt*2+1]);
        }

        __syncthreads();                 // all warps done reading buf cur
        if (kt + 2 < ntiles) load_tile(kt + 2, cur);
        cp_commit();
        cp_wait1();                      // tile kt+1 resident
        __syncthreads();
    }

    #pragma unroll
    for (int mt = 0; mt < 2; mt++) {
        int row = m0 + wm + mt * 16 + g;
        #pragma unroll
        for (int nt = 0; nt < 4; nt++) {
            int col = n0 + wn + nt * 8 + 2 * t;
            float2 r01 = { acc[mt][nt][0], acc[mt][nt][1] };
            float2 r23 = { acc[mt][nt][2], acc[mt][nt][3] };
            float2 bb = *(const float2*)&bias[col];
            r01.x += bb.x; r01.y += bb.y;
            r23.x += bb.x; r23.y += bb.y;
            float2 e0 = *(const float2*)&resid[(size_t)row * N + col];
            float2 e1 = *(const float2*)&resid[(size_t)(row + 8) * N + col];
            r01.x += e0.x; r01.y += e0.y;
            r23.x += e1.x; r23.y += e1.y;
            *(float2*)&Cf[(size_t)row * N + col]       = r01;
            *(float2*)&Cf[(size_t)(row + 8) * N + col] = r23;
        }
    }
}

// ---------------------------------------------------------------------------
// fp16 flash attention (frozen round-14 best): FA2 register-P, base-2 f16x2
// softmax, tensor-core l, record-max vote skip.
// ---------------------------------------------------------------------------
#define KVROWS 128
#define KSTG (KVROWS * 72)                       // 9216 halves (K per stage)
#define STG2 (2 * KSTG)                          // K+V per stage, halves
#define ATTN_SMEM (3 * STG2 * 2)                 // 110592 bytes

__global__ __launch_bounds__(256, 2) void attn_h(
    const __half* __restrict__ Qg, const __half* __restrict__ Kg,
    const __half* __restrict__ Vg, __half* __restrict__ Og)
{
    extern __shared__ __half smh[];
    __half* Qs = smh + 2 * STG2;    // overlaps stage 2 (consumed pre-loop)
    const uint32_t sbase  = (uint32_t)__cvta_generic_to_shared(smh);
    const uint32_t qsbase = (uint32_t)__cvta_generic_to_shared(Qs);

    const int tid  = threadIdx.x;
    const int lane = tid & 31, warp = tid >> 5;
    const int g = lane >> 2, t = lane & 3;
    const int Rr = warp * 16;
    const int it = blockIdx.x, h = blockIdx.y, b = blockIdx.z;

    const __half* qb = Qg + ((size_t)b * NN + it * 128) * INNER + h * DH;
    const __half* kb = Kg + (size_t)b * MM * INNER + h * DH;
    const __half* vb = Vg + (size_t)b * MM * INNER + h * DH;

    const int a_row = lane & 15, a_col = (lane >> 4) * 8;
    const int k_row = (lane & 7) + ((lane >> 4) & 1) * 8;
    const int k_col = ((lane >> 3) & 1) * 8;
    const int v_row = (lane & 7) + ((lane >> 3) & 1) * 8;
    const int v_col = ((lane >> 4) & 1) * 8;

    auto load_chunk = [&](int buf, int j0) {
        __half* Ks = smh + buf * STG2;
        __half* Vs = Ks + KSTG;
        #pragma unroll
        for (int i = 0; i < 4; i++) {
            int id = tid + i * 256;
            int r = id >> 3, c = (id & 7) * 8;
            cp16g(&Ks[r * 72 + c], &kb[(size_t)(j0 + r) * INNER + c]);
            cp16g(&Vs[r * 72 + c], &vb[(size_t)(j0 + r) * INNER + c]);
        }
    };

    #pragma unroll
    for (int i = 0; i < 4; i++) {
        int id = tid + i * 256;
        int r = id >> 3, c = (id & 7) * 8;
        cp16g(&Qs[r * 72 + c], &qb[(size_t)r * INNER + c]);
    }
    cp_commit();                 // group: Q
    load_chunk(0, 0);
    cp_commit();                 // group: chunk0
    load_chunk(1, KVROWS);
    cp_commit();                 // group: chunk1
    cp_wait2();                  // Q resident
    __syncthreads();

    uint32_t qf[4][4];
    #pragma unroll
    for (int ks = 0; ks < 4; ks++) {
        uint32_t addr = qsbase + (uint32_t)(((Rr + a_row) * 72 + ks * 16 + a_col) << 1);
        ldsm4(qf[ks][0], qf[ks][1], qf[ks][2], qf[ks][3], addr);
    }
    __syncthreads();             // Q reads done before stage-2 reload

    float of[8][4];
    #pragma unroll
    for (int i = 0; i < 8; i++)
        #pragma unroll
        for (int q = 0; q < 4; q++) of[i][q] = 0.f;
    float lacc[4] = {0.f, 0.f, 0.f, 0.f};
    float m0r = -INFINITY, m1r = -INFINITY;

    const int nch = MM / KVROWS;   // 16
    for (int ch = 0; ch < nch; ch++) {
        const int cur = ch % 3;
        if (ch + 2 < nch) load_chunk((ch + 2) % 3, (ch + 2) * KVROWS);
        cp_commit();

        const uint32_t kbase = sbase + (uint32_t)(cur * STG2) * 2;
        const uint32_t vbase = kbase + (uint32_t)KSTG * 2;

        #pragma unroll
        for (int sub = 0; sub < 2; sub++) {
            const int roff = sub * 64;

            float sacc[8][4];
            #pragma unroll
            for (int i = 0; i < 8; i++)
                #pragma unroll
                for (int q = 0; q < 4; q++) sacc[i][q] = 0.f;
            #pragma unroll
            for (int ks = 0; ks < 4; ks++) {
                #pragma unroll
                for (int n2 = 0; n2 < 4; n2++) {
                    uint32_t kf0, kf1, kf2, kf3;
                    uint32_t addr = kbase +
                        (uint32_t)(((roff + n2 * 16 + k_row) * 72 + ks * 16 + k_col) << 1);
                    ldsm4(kf0, kf1, kf2, kf3, addr);
                    mma16(sacc[n2*2],   qf[ks][0], qf[ks][1], qf[ks][2], qf[ks][3], kf0, kf1);
                    mma16(sacc[n2*2+1], qf[ks][0], qf[ks][1], qf[ks][2], qf[ks][3], kf2, kf3);
                }
            }

            float rmax0 = -INFINITY, rmax1 = -INFINITY;
            #pragma unroll
            for (int nt = 0; nt < 8; nt++) {
                rmax0 = fmaxf(rmax0, fmaxf(sacc[nt][0], sacc[nt][1]));
                rmax1 = fmaxf(rmax1, fmaxf(sacc[nt][2], sacc[nt][3]));
            }

            float mn0 = m0r, mn1 = m1r;
            if (__any_sync(0xffffffffu, (rmax0 > m0r) || (rmax1 > m1r))) {
                rmax0 = fmaxf(rmax0, __shfl_xor_sync(0xffffffffu, rmax0, 1));
                rmax0 = fmaxf(rmax0, __shfl_xor_sync(0xffffffffu, rmax0, 2));
                rmax1 = fmaxf(rmax1, __shfl_xor_sync(0xffffffffu, rmax1, 1));
                rmax1 = fmaxf(rmax1, __shfl_xor_sync(0xffffffffu, rmax1, 2));
                mn0 = fmaxf(m0r, rmax0);
                mn1 = fmaxf(m1r, rmax1);
                float c0 = exp2f(m0r - mn0), c1 = exp2f(m1r - mn1);
                m0r = mn0; m1r = mn1;
                #pragma unroll
                for (int nt = 0; nt < 8; nt++) {
                    of[nt][0] *= c0; of[nt][1] *= c0;
                    of[nt][2] *= c1; of[nt][3] *= c1;
                }
                lacc[0] *= c0;
                lacc[2] *= c1;
            }

            uint32_t pf[4][4];
            #pragma unroll
            for (int ks = 0; ks < 4; ks++) {
                #pragma unroll
                for (int half = 0; half < 2; half++) {
                    const int nt = 2 * ks + half;
                    __half2 e01 = h2exp2(__floats2half2_rn(sacc[nt][0] - mn0, sacc[nt][1] - mn0));
                    __half2 e23 = h2exp2(__floats2half2_rn(sacc[nt][2] - mn1, sacc[nt][3] - mn1));
                    pf[ks][2*half]   = h2_as_u32(e01);
                    pf[ks][2*half+1] = h2_as_u32(e23);
                }
            }

            #pragma unroll
            for (int ks = 0; ks < 4; ks++) {
                mma16(lacc, pf[ks][0], pf[ks][1], pf[ks][2], pf[ks][3],
                      H2_ONES, H2_ONES);
                #pragma unroll
                for (int n2 = 0; n2 < 4; n2++) {
                    uint32_t vf0, vf1, vf2, vf3;
                    uint32_t addr = vbase +
                        (uint32_t)(((roff + ks * 16 + v_row) * 72 + n2 * 16 + v_col) << 1);
                    ldsm4t(vf0, vf1, vf2, vf3, addr);
                    mma16(of[n2*2],   pf[ks][0], pf[ks][1], pf[ks][2], pf[ks][3], vf0, vf1);
                    mma16(of[n2*2+1], pf[ks][0], pf[ks][1], pf[ks][2], pf[ks][3], vf2, vf3);
                }
            }
        }

        cp_wait1();
        __syncthreads();
    }

    float inv0 = 1.f / lacc[0], inv1 = 1.f / lacc[2];
    int row0 = it * 128 + Rr + g, row1 = row0 + 8;
    #pragma unroll
    for (int nt = 0; nt < 8; nt++) {
        *(__half2*)&Og[((size_t)b * NN + row0) * INNER + h * DH + nt * 8 + 2 * t] =
            __floats2half2_rn(of[nt][0] * inv0, of[nt][1] * inv0);
        *(__half2*)&Og[((size_t)b * NN + row1) * INNER + h * DH + nt * 8 + 2 * t] =
            __floats2half2_rn(of[nt][2] * inv1, of[nt][3] * inv1);
    }
}

// ---------------------------------------------------------------------------
// Launch
// ---------------------------------------------------------------------------
extern "C" void kernel_launch(void* const* d_in, const int* in_sizes, int n_in,
                              void* d_out, int out_size)
{
    (void)in_sizes; (void)n_in; (void)out_size;
    const float* x     = (const float*)d_in[0];
    const float* cond  = (const float*)d_in[1];
    const float* lnx_g = (const float*)d_in[2];
    const float* lnx_b = (const float*)d_in[3];
    const float* lnc_g = (const float*)d_in[4];
    const float* lnc_b = (const float*)d_in[5];
    const float* Wq    = (const float*)d_in[6];
    const float* Wk    = (const float*)d_in[7];
    const float* Wv    = (const float*)d_in[8];
    const float* Wo    = (const float*)d_in[9];
    const float* bo    = (const float*)d_in[10];
    const float* lnf_g = (const float*)d_in[11];
    const float* lnf_b = (const float*)d_in[12];
    float* out = (float*)d_out;

    __half *q, *k, *v, *ao;
    float *y;
    cudaGetSymbolAddress((void**)&q,  g_q);
    cudaGetSymbolAddress((void**)&k,  g_k);
    cudaGetSymbolAddress((void**)&v,  g_v);
    cudaGetSymbolAddress((void**)&ao, g_ao);
    cudaGetSymbolAddress((void**)&y,  g_y);

    cudaFuncSetAttribute(qkv_gemm, cudaFuncAttributeMaxDynamicSharedMemorySize, GEMM_SMEM);
    cudaFuncSetAttribute(gemm_o,  cudaFuncAttributeMaxDynamicSharedMemorySize, GEMMO_SMEM);
    cudaFuncSetAttribute(attn_h,  cudaFuncAttributeMaxDynamicSharedMemorySize, ATTN_SMEM);

    prep_kernel<<<LN_BLK + F2H_BLK, 256>>>(x, lnx_g, lnx_b, cond, lnc_g, lnc_b,
                                           (const float4*)Wq, (const float4*)Wk,
                                           (const float4*)Wv, (const float4*)Wo);

    dim3 gthr(256);
    qkv_gemm<<<dim3(INNER / 128, (BB * NN) / 128, 3), gthr, GEMM_SMEM>>>();

    dim3 ga(NN / 128, HH, BB);
    attn_h<<<ga, gthr, ATTN_SMEM>>>(q, k, v, ao);

    gemm_o<<<dim3(DQ / 128, (BB * NN) / 64), gthr, GEMMO_SMEM>>>(bo, x);

    ln_out<<<(BB * NN) / 8, 256>>>(y, lnf_g, lnf_b, out);
}

// round 17
// speedup vs baseline: 1.0105x; 1.0105x over previous
#include <cuda_runtime.h>
#include <cuda_fp16.h>
#include <math.h>
#include <stdint.h>

#define BB 4
#define NN 2048
#define MM 2048
#define DQ 512
#define DC 768
#define HH 8
#define DH 64
#define INNER 512

// 0.125 * log2(e): folds attention scale + base-2 exp domain into Q projection.
#define QSCALE 0.18033688011112042f

// ---------------------------------------------------------------------------
// Scratch (device globals -- no allocation allowed)
// ---------------------------------------------------------------------------
__device__ __half g_xn[BB*NN*DQ];
__device__ __half g_cn[BB*MM*DC];
__device__ __half g_q [BB*NN*INNER];
__device__ __half g_k [BB*MM*INNER];
__device__ __half g_v [BB*MM*INNER];
__device__ __half g_ao[BB*NN*INNER];
__device__ float  g_y [BB*NN*DQ];
__device__ __half g_wq[DQ*INNER];
__device__ __half g_wk[DC*INNER];
__device__ __half g_wv[DC*INNER];
__device__ __half g_wo[INNER*DQ];

// ---------------------------------------------------------------------------
// PTX helpers
// ---------------------------------------------------------------------------
__device__ __forceinline__ uint32_t h2_as_u32(__half2 h) {
    return *reinterpret_cast<uint32_t*>(&h);
}
__device__ __forceinline__ void cp16g(void* dst_smem, const void* src) {
    uint32_t d = (uint32_t)__cvta_generic_to_shared(dst_smem);
    asm volatile("cp.async.cg.shared.global [%0], [%1], 16;" :: "r"(d), "l"(src));
}
__device__ __forceinline__ void cp_commit() {
    asm volatile("cp.async.commit_group;" ::: "memory");
}
__device__ __forceinline__ void cp_wait1() {
    asm volatile("cp.async.wait_group 1;" ::: "memory");
}
__device__ __forceinline__ void cp_wait2() {
    asm volatile("cp.async.wait_group 2;" ::: "memory");
}
__device__ __forceinline__ void ldsm4(uint32_t& r0, uint32_t& r1, uint32_t& r2, uint32_t& r3, uint32_t a) {
    asm volatile("ldmatrix.sync.aligned.m8n8.x4.shared.b16 {%0,%1,%2,%3}, [%4];"
                 : "=r"(r0), "=r"(r1), "=r"(r2), "=r"(r3) : "r"(a));
}
__device__ __forceinline__ void ldsm4t(uint32_t& r0, uint32_t& r1, uint32_t& r2, uint32_t& r3, uint32_t a) {
    asm volatile("ldmatrix.sync.aligned.m8n8.x4.trans.shared.b16 {%0,%1,%2,%3}, [%4];"
                 : "=r"(r0), "=r"(r1), "=r"(r2), "=r"(r3) : "r"(a));
}
__device__ __forceinline__ void mma16(float* c, uint32_t a0, uint32_t a1, uint32_t a2, uint32_t a3,
                                      uint32_t b0, uint32_t b1) {
    asm volatile(
        "mma.sync.aligned.m16n8k16.row.col.f32.f16.f16.f32 "
        "{%0,%1,%2,%3},{%4,%5,%6,%7},{%8,%9},{%0,%1,%2,%3};"
        : "+f"(c[0]), "+f"(c[1]), "+f"(c[2]), "+f"(c[3])
        : "r"(a0), "r"(a1), "r"(a2), "r"(a3), "r"(b0), "r"(b1));
}

// all-ones fp16x2 B fragment (1.0, 1.0)
#define H2_ONES 0x3C003C00u

// ---------------------------------------------------------------------------
// Fused prep: input LayerNorms (warp-per-row) + weight f2h, one launch.
// ---------------------------------------------------------------------------
#define LN_ROWS (BB*NN + BB*MM)          // 16384
#define LN_BLK  (LN_ROWS / 8)            // 2048
#define N4_WQ (DQ*INNER/4)
#define N4_WK (DC*INNER/4)
#define N4_WV (DC*INNER/4)
#define N4_WO (INNER*DQ/4)
#define N4_TOT (N4_WQ + N4_WK + N4_WV + N4_WO)   // 327680
#define F2H_BLK ((N4_TOT + 255) / 256)   // 1280

__global__ __launch_bounds__(256) void prep_kernel(
    const float* __restrict__ x,    const float* __restrict__ xg, const float* __restrict__ xb,
    const float* __restrict__ cnd,  const float* __restrict__ cg, const float* __restrict__ cb,
    const float4* __restrict__ wq, const float4* __restrict__ wk,
    const float4* __restrict__ wv, const float4* __restrict__ wo)
{
    if (blockIdx.x >= LN_BLK) {
        int i = (blockIdx.x - LN_BLK) * blockDim.x + threadIdx.x;
        if (i >= N4_TOT) return;
        const float4* src;
        __half2* dst;
        int j = i;
        if (j < N4_WQ)                 { src = wq; dst = (__half2*)g_wq; }
        else if ((j -= N4_WQ) < N4_WK) { src = wk; dst = (__half2*)g_wk; }
        else if ((j -= N4_WK) < N4_WV) { src = wv; dst = (__half2*)g_wv; }
        else { j -= N4_WV;               src = wo; dst = (__half2*)g_wo; }
        float4 v = src[j];
        dst[2*j]   = __floats2half2_rn(v.x, v.y);
        dst[2*j+1] = __floats2half2_rn(v.z, v.w);
        return;
    }

    const int warp = threadIdx.x >> 5, lane = threadIdx.x & 31;
    int row = blockIdx.x * 8 + warp;

    const float* in; const float* gw; const float* bw; __half* out; int D;
    if (row < BB * NN) { in = x; gw = xg; bw = xb; out = g_xn; D = DQ; }
    else { row -= BB * NN; in = cnd; gw = cg; bw = cb; out = g_cn; D = DC; }
    const int nv = D / 128;

    const float4* x4 = (const float4*)(in + (size_t)row * D);
    float4 v[6];
    float s = 0.f, sq = 0.f;
    #pragma unroll 6
    for (int i = 0; i < nv; i++) {
        v[i] = x4[lane + 32 * i];
        s  += v[i].x + v[i].y + v[i].z + v[i].w;
        sq += v[i].x * v[i].x + v[i].y * v[i].y + v[i].z * v[i].z + v[i].w * v[i].w;
    }
    #pragma unroll
    for (int off = 16; off; off >>= 1) {
        s  += __shfl_xor_sync(0xffffffffu, s,  off);
        sq += __shfl_xor_sync(0xffffffffu, sq, off);
    }
    const float mu   = s * (1.0f / D);
    const float var  = sq * (1.0f / D) - mu * mu;
    const float rstd = rsqrtf(var + 1e-5f);

    const float4* g4 = (const float4*)gw;
    const float4* b4 = (const float4*)bw;
    __half2* o2 = (__half2*)out + (size_t)row * (D / 2);
    #pragma unroll 6
    for (int i = 0; i < nv; i++) {
        float4 g = g4[lane + 32 * i], b = b4[lane + 32 * i];
        float rx = (v[i].x - mu) * rstd * g.x + b.x;
        float ry = (v[i].y - mu) * rstd * g.y + b.y;
        float rz = (v[i].z - mu) * rstd * g.z + b.z;
        float rw = (v[i].w - mu) * rstd * g.w + b.w;
        o2[(lane + 32 * i) * 2]     = __floats2half2_rn(rx, ry);
        o2[(lane + 32 * i) * 2 + 1] = __floats2half2_rn(rz, rw);
    }
}

// Warp-per-row final LayerNorm (fp32 in/out, D=512)
__global__ __launch_bounds__(256) void ln_out(
    const float* __restrict__ in, const float* __restrict__ gw,
    const float* __restrict__ bw, float* __restrict__ outp)
{
    const int warp = threadIdx.x >> 5, lane = threadIdx.x & 31;
    const int row = blockIdx.x * 8 + warp;

    const float4* x4 = (const float4*)(in + (size_t)row * DQ);
    float4 v[4];
    float s = 0.f, sq = 0.f;
    #pragma unroll
    for (int i = 0; i < 4; i++) {
        v[i] = x4[lane + 32 * i];
        s  += v[i].x + v[i].y + v[i].z + v[i].w;
        sq += v[i].x * v[i].x + v[i].y * v[i].y + v[i].z * v[i].z + v[i].w * v[i].w;
    }
    #pragma unroll
    for (int off = 16; off; off >>= 1) {
        s  += __shfl_xor_sync(0xffffffffu, s,  off);
        sq += __shfl_xor_sync(0xffffffffu, sq, off);
    }
    const float mu   = s * (1.0f / DQ);
    const float var  = sq * (1.0f / DQ) - mu * mu;
    const float rstd = rsqrtf(var + 1e-5f);

    const float4* g4 = (const float4*)gw;
    const float4* b4 = (const float4*)bw;
    float4* o4 = (float4*)(outp + (size_t)row * DQ);
    #pragma unroll
    for (int i = 0; i < 4; i++) {
        float4 g = g4[lane + 32 * i], b = b4[lane + 32 * i], r;
        r.x = (v[i].x - mu) * rstd * g.x + b.x;
        r.y = (v[i].y - mu) * rstd * g.y + b.y;
        r.z = (v[i].z - mu) * rstd * g.z + b.z;
        r.w = (v[i].w - mu) * rstd * g.w + b.w;
        o4[lane + 32 * i] = r;
    }
}

// ---------------------------------------------------------------------------
// GEMM tile config (128x128, 3-stage) -- shared by qkv_gemm and gemm_o
// ---------------------------------------------------------------------------
#define GS_A 9216                      // 128*72 halves
#define GS_B 8704                      // 64*136 halves
#define GSTG (GS_A + GS_B)             // 17920 halves / stage
#define GEMM_SMEM (3 * GSTG * 2)       // 107520 bytes

// ---------------------------------------------------------------------------
// Merged Q/K/V projection: LPT order (long K/V first, short Q last).
// ---------------------------------------------------------------------------
__global__ __launch_bounds__(256, 2) void qkv_gemm()
{
    extern __shared__ __half smh[];
    const uint32_t sbase = (uint32_t)__cvta_generic_to_shared(smh);

    const __half* A; const __half* W; __half* C; int K; float osc;
    if (blockIdx.z == 0)      { A = g_cn; W = g_wk; C = g_k; K = DC; osc = 1.0f; }
    else if (blockIdx.z == 1) { A = g_cn; W = g_wv; C = g_v; K = DC; osc = 1.0f; }
    else                      { A = g_xn; W = g_wq; C = g_q; K = DQ; osc = QSCALE; }

    const int tid = threadIdx.x;
    const int lane = tid & 31, warp = tid >> 5;
    const int wm = (warp >> 2) * 64;
    const int wn = (warp & 3) * 32;
    const int m0 = blockIdx.y * 128;
    const int n0 = blockIdx.x * 128;
    const int g = lane >> 2, t = lane & 3;

    const int a_row = lane & 15, a_col = (lane >> 4) * 8;
    const int b_row = (lane & 7) + ((lane >> 3) & 1) * 8;
    const int b_col = ((lane >> 4) & 1) * 8;

    float acc[4][4][4];
    #pragma unroll
    for (int i = 0; i < 4; i++)
        #pragma unroll
        for (int j = 0; j < 4; j++)
            #pragma unroll
            for (int q = 0; q < 4; q++) acc[i][j][q] = 0.f;

    auto load_tile = [&](int kt, int buf) {
        int k0 = kt * 64;
        __half* As = smh + buf * GSTG;
        __half* Bs = smh + buf * GSTG + GS_A;
        #pragma unroll
        for (int i = 0; i < 4; i++) {
            int id = tid + i * 256;
            int ar = id >> 3, ac = (id & 7) * 8;
            cp16g(&As[ar * 72 + ac], &A[(size_t)(m0 + ar) * K + k0 + ac]);
            int br = id >> 4, bc = (id & 15) * 8;
            cp16g(&Bs[br * 136 + bc], &W[(size_t)(k0 + br) * INNER + n0 + bc]);
        }
    };

    const int ntiles = K / 64;
    load_tile(0, 0); cp_commit();
    load_tile(1, 1); cp_commit();
    cp_wait1();
    __syncthreads();

    for (int kt = 0; kt < ntiles; kt++) {
        const int cur = kt % 3;
        if (kt + 2 < ntiles) load_tile(kt + 2, (kt + 2) % 3);
        cp_commit();

        const uint32_t abase = sbase + (uint32_t)(cur * GSTG) * 2;
        const uint32_t bbase = abase + (uint32_t)GS_A * 2;

        #pragma unroll
        for (int ks = 0; ks < 4; ks++) {
            uint32_t af[4][4];
            #pragma unroll
            for (int mt = 0; mt < 4; mt++) {
                uint32_t addr = abase +
                    (uint32_t)(((wm + mt * 16 + a_row) * 72 + ks * 16 + a_col) << 1);
                ldsm4(af[mt][0], af[mt][1], af[mt][2], af[mt][3], addr);
            }
            uint32_t bf[8];
            #pragma unroll
            for (int n2 = 0; n2 < 2; n2++) {
                uint32_t addr = bbase +
                    (uint32_t)(((ks * 16 + b_row) * 136 + wn + n2 * 16 + b_col) << 1);
                ldsm4t(bf[n2*4], bf[n2*4+1], bf[n2*4+2], bf[n2*4+3], addr);
            }
            #pragma unroll
            for (int mt = 0; mt < 4; mt++)
                #pragma unroll
                for (int nt = 0; nt < 4; nt++)
                    mma16(acc[mt][nt], af[mt][0], af[mt][1], af[mt][2], af[mt][3],
                          bf[nt*2], bf[nt*2+1]);
        }

        cp_wait1();
        __syncthreads();
    }

    #pragma unroll
    for (int mt = 0; mt < 4; mt++) {
        int row = m0 + wm + mt * 16 + g;
        #pragma unroll
        for (int nt = 0; nt < 4; nt++) {
            int col = n0 + wn + nt * 8 + 2 * t;
            *(__half2*)&C[(size_t)row * INNER + col] =
                __floats2half2_rn(acc[mt][nt][0] * osc, acc[mt][nt][1] * osc);
            *(__half2*)&C[(size_t)(row + 8) * INNER + col] =
                __floats2half2_rn(acc[mt][nt][2] * osc, acc[mt][nt][3] * osc);
        }
    }
}

// ---------------------------------------------------------------------------
// O-projection GEMM (R15 config: 128x128 tile, 3-stage, fp32+bias+resid)
// ---------------------------------------------------------------------------
__global__ __launch_bounds__(256, 2) void gemm_o(
    const float* __restrict__ bias, const float* __restrict__ resid)
{
    extern __shared__ __half smh[];
    const uint32_t sbase = (uint32_t)__cvta_generic_to_shared(smh);
    const __half* A = g_ao;
    const __half* W = g_wo;
    float* Cf = g_y;
    const int K = INNER, N = DQ;

    const int tid = threadIdx.x;
    const int lane = tid & 31, warp = tid >> 5;
    const int wm = (warp >> 2) * 64;
    const int wn = (warp & 3) * 32;
    const int m0 = blockIdx.y * 128;
    const int n0 = blockIdx.x * 128;
    const int g = lane >> 2, t = lane & 3;

    const int a_row = lane & 15, a_col = (lane >> 4) * 8;
    const int b_row = (lane & 7) + ((lane >> 3) & 1) * 8;
    const int b_col = ((lane >> 4) & 1) * 8;

    float acc[4][4][4];
    #pragma unroll
    for (int i = 0; i < 4; i++)
        #pragma unroll
        for (int j = 0; j < 4; j++)
            #pragma unroll
            for (int q = 0; q < 4; q++) acc[i][j][q] = 0.f;

    auto load_tile = [&](int kt, int buf) {
        int k0 = kt * 64;
        __half* As = smh + buf * GSTG;
        __half* Bs = smh + buf * GSTG + GS_A;
        #pragma unroll
        for (int i = 0; i < 4; i++) {
            int id = tid + i * 256;
            int ar = id >> 3, ac = (id & 7) * 8;
            cp16g(&As[ar * 72 + ac], &A[(size_t)(m0 + ar) * K + k0 + ac]);
            int br = id >> 4, bc = (id & 15) * 8;
            cp16g(&Bs[br * 136 + bc], &W[(size_t)(k0 + br) * N + n0 + bc]);
        }
    };

    const int ntiles = K / 64;
    load_tile(0, 0); cp_commit();
    load_tile(1, 1); cp_commit();
    cp_wait1();
    __syncthreads();

    for (int kt = 0; kt < ntiles; kt++) {
        const int cur = kt % 3;
        if (kt + 2 < ntiles) load_tile(kt + 2, (kt + 2) % 3);
        cp_commit();

        const uint32_t abase = sbase + (uint32_t)(cur * GSTG) * 2;
        const uint32_t bbase = abase + (uint32_t)GS_A * 2;

        #pragma unroll
        for (int ks = 0; ks < 4; ks++) {
            uint32_t af[4][4];
            #pragma unroll
            for (int mt = 0; mt < 4; mt++) {
                uint32_t addr = abase +
                    (uint32_t)(((wm + mt * 16 + a_row) * 72 + ks * 16 + a_col) << 1);
                ldsm4(af[mt][0], af[mt][1], af[mt][2], af[mt][3], addr);
            }
            uint32_t bf[8];
            #pragma unroll
            for (int n2 = 0; n2 < 2; n2++) {
                uint32_t addr = bbase +
                    (uint32_t)(((ks * 16 + b_row) * 136 + wn + n2 * 16 + b_col) << 1);
                ldsm4t(bf[n2*4], bf[n2*4+1], bf[n2*4+2], bf[n2*4+3], addr);
            }
            #pragma unroll
            for (int mt = 0; mt < 4; mt++)
                #pragma unroll
                for (int nt = 0; nt < 4; nt++)
                    mma16(acc[mt][nt], af[mt][0], af[mt][1], af[mt][2], af[mt][3],
                          bf[nt*2], bf[nt*2+1]);
        }

        cp_wait1();
        __syncthreads();
    }

    #pragma unroll
    for (int mt = 0; mt < 4; mt++) {
        int row = m0 + wm + mt * 16 + g;
        #pragma unroll
        for (int nt = 0; nt < 4; nt++) {
            int col = n0 + wn + nt * 8 + 2 * t;
            float2 r01 = { acc[mt][nt][0], acc[mt][nt][1] };
            float2 r23 = { acc[mt][nt][2], acc[mt][nt][3] };
            float2 bb = *(const float2*)&bias[col];
            r01.x += bb.x; r01.y += bb.y;
            r23.x += bb.x; r23.y += bb.y;
            float2 e0 = *(const float2*)&resid[(size_t)row * N + col];
            float2 e1 = *(const float2*)&resid[(size_t)(row + 8) * N + col];
            r01.x += e0.x; r01.y += e0.y;
            r23.x += e1.x; r23.y += e1.y;
            *(float2*)&Cf[(size_t)row * N + col]       = r01;
            *(float2*)&Cf[(size_t)(row + 8) * N + col] = r23;
        }
    }
}

// ---------------------------------------------------------------------------
// fp16 flash attention: FA2 register-P, base-2 f16x2 softmax, tensor-core l,
// record-max vote skip. NEW: sub-blocks software-pipelined
// (S0 -> soft0 -> S1 -> PV0 -> soft1 -> PV1) so softmax scalar work overlaps
// in-flight MMAs.
// ---------------------------------------------------------------------------
#define KVROWS 128
#define KSTG (KVROWS * 72)                       // 9216 halves (K per stage)
#define STG2 (2 * KSTG)                          // K+V per stage, halves
#define ATTN_SMEM (3 * STG2 * 2)                 // 110592 bytes

__global__ __launch_bounds__(256, 2) void attn_h(
    const __half* __restrict__ Qg, const __half* __restrict__ Kg,
    const __half* __restrict__ Vg, __half* __restrict__ Og)
{
    extern __shared__ __half smh[];
    __half* Qs = smh + 2 * STG2;    // overlaps stage 2 (consumed pre-loop)
    const uint32_t sbase  = (uint32_t)__cvta_generic_to_shared(smh);
    const uint32_t qsbase = (uint32_t)__cvta_generic_to_shared(Qs);

    const int tid  = threadIdx.x;
    const int lane = tid & 31, warp = tid >> 5;
    const int g = lane >> 2, t = lane & 3;
    const int Rr = warp * 16;
    const int it = blockIdx.x, h = blockIdx.y, b = blockIdx.z;

    const __half* qb = Qg + ((size_t)b * NN + it * 128) * INNER + h * DH;
    const __half* kb = Kg + (size_t)b * MM * INNER + h * DH;
    const __half* vb = Vg + (size_t)b * MM * INNER + h * DH;

    const int a_row = lane & 15, a_col = (lane >> 4) * 8;
    const int k_row = (lane & 7) + ((lane >> 4) & 1) * 8;
    const int k_col = ((lane >> 3) & 1) * 8;
    const int v_row = (lane & 7) + ((lane >> 3) & 1) * 8;
    const int v_col = ((lane >> 4) & 1) * 8;

    auto load_chunk = [&](int buf, int j0) {
        __half* Ks = smh + buf * STG2;
        __half* Vs = Ks + KSTG;
        #pragma unroll
        for (int i = 0; i < 4; i++) {
            int id = tid + i * 256;
            int r = id >> 3, c = (id & 7) * 8;
            cp16g(&Ks[r * 72 + c], &kb[(size_t)(j0 + r) * INNER + c]);
            cp16g(&Vs[r * 72 + c], &vb[(size_t)(j0 + r) * INNER + c]);
        }
    };

    #pragma unroll
    for (int i = 0; i < 4; i++) {
        int id = tid + i * 256;
        int r = id >> 3, c = (id & 7) * 8;
        cp16g(&Qs[r * 72 + c], &qb[(size_t)r * INNER + c]);
    }
    cp_commit();                 // group: Q
    load_chunk(0, 0);
    cp_commit();                 // group: chunk0
    load_chunk(1, KVROWS);
    cp_commit();                 // group: chunk1
    cp_wait2();                  // Q resident
    __syncthreads();

    uint32_t qf[4][4];
    #pragma unroll
    for (int ks = 0; ks < 4; ks++) {
        uint32_t addr = qsbase + (uint32_t)(((Rr + a_row) * 72 + ks * 16 + a_col) << 1);
        ldsm4(qf[ks][0], qf[ks][1], qf[ks][2], qf[ks][3], addr);
    }
    __syncthreads();             // Q reads done before stage-2 reload

    float of[8][4];
    #pragma unroll
    for (int i = 0; i < 8; i++)
        #pragma unroll
        for (int q = 0; q < 4; q++) of[i][q] = 0.f;
    float lacc[4] = {0.f, 0.f, 0.f, 0.f};
    float m0r = -INFINITY, m1r = -INFINITY;

    const int nch = MM / KVROWS;   // 16
    for (int ch = 0; ch < nch; ch++) {
        const int cur = ch % 3;
        if (ch + 2 < nch) load_chunk((ch + 2) % 3, (ch + 2) * KVROWS);
        cp_commit();

        const uint32_t kbase = sbase + (uint32_t)(cur * STG2) * 2;
        const uint32_t vbase = kbase + (uint32_t)KSTG * 2;

        // --- helpers on this chunk ---
        auto compute_S = [&](int roff, float (&sacc)[8][4]) {
            #pragma unroll
            for (int i = 0; i < 8; i++)
                #pragma unroll
                for (int q = 0; q < 4; q++) sacc[i][q] = 0.f;
            #pragma unroll
            for (int ks = 0; ks < 4; ks++) {
                #pragma unroll
                for (int n2 = 0; n2 < 4; n2++) {
                    uint32_t kf0, kf1, kf2, kf3;
                    uint32_t addr = kbase +
                        (uint32_t)(((roff + n2 * 16 + k_row) * 72 + ks * 16 + k_col) << 1);
                    ldsm4(kf0, kf1, kf2, kf3, addr);
                    mma16(sacc[n2*2],   qf[ks][0], qf[ks][1], qf[ks][2], qf[ks][3], kf0, kf1);
                    mma16(sacc[n2*2+1], qf[ks][0], qf[ks][1], qf[ks][2], qf[ks][3], kf2, kf3);
                }
            }
        };

        auto softmax_pf = [&](float (&sacc)[8][4], uint32_t (&pf)[4][4]) {
            float rmax0 = -INFINITY, rmax1 = -INFINITY;
            #pragma unroll
            for (int nt = 0; nt < 8; nt++) {
                rmax0 = fmaxf(rmax0, fmaxf(sacc[nt][0], sacc[nt][1]));
                rmax1 = fmaxf(rmax1, fmaxf(sacc[nt][2], sacc[nt][3]));
            }
            float mn0 = m0r, mn1 = m1r;
            if (__any_sync(0xffffffffu, (rmax0 > m0r) || (rmax1 > m1r))) {
                rmax0 = fmaxf(rmax0, __shfl_xor_sync(0xffffffffu, rmax0, 1));
                rmax0 = fmaxf(rmax0, __shfl_xor_sync(0xffffffffu, rmax0, 2));
                rmax1 = fmaxf(rmax1, __shfl_xor_sync(0xffffffffu, rmax1, 1));
                rmax1 = fmaxf(rmax1, __shfl_xor_sync(0xffffffffu, rmax1, 2));
                mn0 = fmaxf(m0r, rmax0);
                mn1 = fmaxf(m1r, rmax1);
                float c0 = exp2f(m0r - mn0), c1 = exp2f(m1r - mn1);
                m0r = mn0; m1r = mn1;
                #pragma unroll
                for (int nt = 0; nt < 8; nt++) {
                    of[nt][0] *= c0; of[nt][1] *= c0;
                    of[nt][2] *= c1; of[nt][3] *= c1;
                }
                lacc[0] *= c0;
                lacc[2] *= c1;
            }
            #pragma unroll
            for (int ks = 0; ks < 4; ks++) {
                #pragma unroll
                for (int half = 0; half < 2; half++) {
                    const int nt = 2 * ks + half;
                    __half2 e01 = h2exp2(__floats2half2_rn(sacc[nt][0] - mn0, sacc[nt][1] - mn0));
                    __half2 e23 = h2exp2(__floats2half2_rn(sacc[nt][2] - mn1, sacc[nt][3] - mn1));
                    pf[ks][2*half]   = h2_as_u32(e01);
                    pf[ks][2*half+1] = h2_as_u32(e23);
                }
            }
        };

        auto pv = [&](int roff, uint32_t (&pf)[4][4]) {
            #pragma unroll
            for (int ks = 0; ks < 4; ks++) {
                mma16(lacc, pf[ks][0], pf[ks][1], pf[ks][2], pf[ks][3],
                      H2_ONES, H2_ONES);
                #pragma unroll
                for (int n2 = 0; n2 < 4; n2++) {
                    uint32_t vf0, vf1, vf2, vf3;
                    uint32_t addr = vbase +
                        (uint32_t)(((roff + ks * 16 + v_row) * 72 + n2 * 16 + v_col) << 1);
                    ldsm4t(vf0, vf1, vf2, vf3, addr);
                    mma16(of[n2*2],   pf[ks][0], pf[ks][1], pf[ks][2], pf[ks][3], vf0, vf1);
                    mma16(of[n2*2+1], pf[ks][0], pf[ks][1], pf[ks][2], pf[ks][3], vf2, vf3);
                }
            }
        };

        // software-pipelined schedule: S0, soft0, S1, PV0, soft1, PV1
        float sacc0[8][4];
        compute_S(0, sacc0);
        uint32_t pf0[4][4];
        softmax_pf(sacc0, pf0);

        float sacc1[8][4];
        compute_S(64, sacc1);
        pv(0, pf0);

        uint32_t pf1[4][4];
        softmax_pf(sacc1, pf1);
        pv(64, pf1);

        cp_wait1();
        __syncthreads();
    }

    float inv0 = 1.f / lacc[0], inv1 = 1.f / lacc[2];
    int row0 = it * 128 + Rr + g, row1 = row0 + 8;
    #pragma unroll
    for (int nt = 0; nt < 8; nt++) {
        *(__half2*)&Og[((size_t)b * NN + row0) * INNER + h * DH + nt * 8 + 2 * t] =
            __floats2half2_rn(of[nt][0] * inv0, of[nt][1] * inv0);
        *(__half2*)&Og[((size_t)b * NN + row1) * INNER + h * DH + nt * 8 + 2 * t] =
            __floats2half2_rn(of[nt][2] * inv1, of[nt][3] * inv1);
    }
}

// ---------------------------------------------------------------------------
// Launch
// ---------------------------------------------------------------------------
extern "C" void kernel_launch(void* const* d_in, const int* in_sizes, int n_in,
                              void* d_out, int out_size)
{
    (void)in_sizes; (void)n_in; (void)out_size;
    const float* x     = (const float*)d_in[0];
    const float* cond  = (const float*)d_in[1];
    const float* lnx_g = (const float*)d_in[2];
    const float* lnx_b = (const float*)d_in[3];
    const float* lnc_g = (const float*)d_in[4];
    const float* lnc_b = (const float*)d_in[5];
    const float* Wq    = (const float*)d_in[6];
    const float* Wk    = (const float*)d_in[7];
    const float* Wv    = (const float*)d_in[8];
    const float* Wo    = (const float*)d_in[9];
    const float* bo    = (const float*)d_in[10];
    const float* lnf_g = (const float*)d_in[11];
    const float* lnf_b = (const float*)d_in[12];
    float* out = (float*)d_out;

    __half *q, *k, *v, *ao;
    float *y;
    cudaGetSymbolAddress((void**)&q,  g_q);
    cudaGetSymbolAddress((void**)&k,  g_k);
    cudaGetSymbolAddress((void**)&v,  g_v);
    cudaGetSymbolAddress((void**)&ao, g_ao);
    cudaGetSymbolAddress((void**)&y,  g_y);

    cudaFuncSetAttribute(qkv_gemm, cudaFuncAttributeMaxDynamicSharedMemorySize, GEMM_SMEM);
    cudaFuncSetAttribute(gemm_o,  cudaFuncAttributeMaxDynamicSharedMemorySize, GEMM_SMEM);
    cudaFuncSetAttribute(attn_h,  cudaFuncAttributeMaxDynamicSharedMemorySize, ATTN_SMEM);

    prep_kernel<<<LN_BLK + F2H_BLK, 256>>>(x, lnx_g, lnx_b, cond, lnc_g, lnc_b,
                                           (const float4*)Wq, (const float4*)Wk,
                                           (const float4*)Wv, (const float4*)Wo);

    dim3 gthr(256);
    qkv_gemm<<<dim3(INNER / 128, (BB * NN) / 128, 3), gthr, GEMM_SMEM>>>();

    dim3 ga(NN / 128, HH, BB);
    attn_h<<<ga, gthr, ATTN_SMEM>>>(q, k, v, ao);

    gemm_o<<<dim3(DQ / 128, (BB * NN) / 128), gthr, GEMM_SMEM>>>(bo, x);

    ln_out<<<(BB * NN) / 8, 256>>>(y, lnf_g, lnf_b, out);
}